// round 2
// baseline (speedup 1.0000x reference)
#include <cuda_runtime.h>
#include <cstdint>
#include <cstddef>

namespace {
constexpr int kB    = 128;
constexpr int kT    = 65536;
constexpr int kE    = 512;
constexpr int kSmax = 512;

constexpr int BM = 64;
constexpr int BN = 64;
constexpr int BK = 32;
constexpr int LDSS = 68;   // padded stride for transposed smem tiles
}

__device__ int g_nvalid[kB];

// ---------------------------------------------------------------------------
// Kernel A: per-sample mask popcount -> n_valid, plus padding_mask output.
// Mask arrives as int32 (bool widened by the harness): one 0/1 per element.
// ---------------------------------------------------------------------------
__global__ __launch_bounds__(256) void len_mask_kernel(
    const int* __restrict__ mask,
    const int* __restrict__ branch_idx,
    float* __restrict__ out,
    int write_mask)
{
    int b = blockIdx.x;
    int t = threadIdx.x;

    const uint4* p = reinterpret_cast<const uint4*>(mask + (size_t)b * kT);
    int sum = 0;
#pragma unroll 4
    for (int i = t; i < kT / 4; i += 256) {      // kT/4 uint4s, 4 elements each
        uint4 v = p[i];
        sum += (int)((v.x & 1u) + (v.y & 1u) + (v.z & 1u) + (v.w & 1u));
    }
#pragma unroll
    for (int o = 16; o > 0; o >>= 1) sum += __shfl_down_sync(0xffffffffu, sum, o);

    __shared__ int warp_sums[8];
    __shared__ int nv_sh;
    if ((t & 31) == 0) warp_sums[t >> 5] = sum;
    __syncthreads();
    if (t == 0) {
        int tot = 0;
#pragma unroll
        for (int i = 0; i < 8; i++) tot += warp_sums[i];
        int bi = branch_idx[b];
        int w  = 128 << bi;          // 128, 256, 512
        int Sb = kT / w;             // 512, 256, 128
        int nv = tot / w;
        if (nv > Sb) nv = Sb;
        g_nvalid[b] = nv;
        nv_sh = nv;
    }
    __syncthreads();

    if (write_mask) {
        int nv = nv_sh;
        float* mout = out + (size_t)kB * kSmax * kE + (size_t)b * kSmax;
        for (int s = t; s < kSmax; s += 256) mout[s] = (s < nv) ? 1.0f : 0.0f;
    }
}

// ---------------------------------------------------------------------------
// Kernel B: per-sample GEMM  tokens[b] = patches(S_b x w) @ W_i^T(w x E) + bias
// Grid: (E/BN, Smax/BM, B). Blocks fully past n_valid write zeros and exit.
// ---------------------------------------------------------------------------
__global__ __launch_bounds__(256) void branch_gemm_kernel(
    const float* __restrict__ signal,
    const int*   __restrict__ branch_idx,
    const float* __restrict__ W0, const float* __restrict__ b0,
    const float* __restrict__ W1, const float* __restrict__ b1,
    const float* __restrict__ W2, const float* __restrict__ b2,
    float* __restrict__ out)
{
    int b  = blockIdx.z;
    int m0 = blockIdx.y * BM;
    int n0 = blockIdx.x * BN;
    int t  = threadIdx.x;

    float* outb = out + (size_t)b * kSmax * kE;
    int nv = g_nvalid[b];

    if (m0 >= nv) {
        // Entire tile is zero (covers both s >= n_valid and s >= S_b).
        int zr = t >> 4;            // 0..15
        int zc = (t & 15) << 2;     // 0..60
        float4 z = make_float4(0.f, 0.f, 0.f, 0.f);
#pragma unroll
        for (int i = 0; i < 4; i++) {
            *reinterpret_cast<float4*>(outb + (size_t)(m0 + zr + i * 16) * kE + n0 + zc) = z;
        }
        return;
    }

    int bi = branch_idx[b];
    int w  = 128 << bi;
    const float* Wp = (bi == 0) ? W0 : (bi == 1) ? W1 : W2;
    const float* bp = (bi == 0) ? b0 : (bi == 1) ? b1 : b2;

    // Since m0 < nv <= S_b and S_b is a multiple of 64, rows m0..m0+63 are
    // all < S_b -> every A load below is in-bounds. No predicates needed.
    const float* A  = signal + (size_t)b * kT + (size_t)m0 * w;
    const float* Bm = Wp + (size_t)n0 * w;

    __shared__ float As[BK * LDSS];   // As[k][m]
    __shared__ float Bs[BK * LDSS];   // Bs[k][n]

    float acc[4][4];
#pragma unroll
    for (int i = 0; i < 4; i++)
#pragma unroll
        for (int j = 0; j < 4; j++) acc[i][j] = 0.f;

    // Load mapping: 8 threads per row, float4 along k; two row-halves per thread.
    int lrow = t >> 3;          // 0..31
    int lcol = (t & 7) << 2;    // k offset 0..28

    // Compute mapping: 16x16 thread grid, 4x4 microtile.
    int tn = (t & 15) << 2;     // 0..60
    int tm = (t >> 4) << 2;     // 0..60

    for (int kk = 0; kk < w; kk += BK) {
        float4 a0 = *reinterpret_cast<const float4*>(A  + (size_t)lrow        * w + kk + lcol);
        float4 a1 = *reinterpret_cast<const float4*>(A  + (size_t)(lrow + 32) * w + kk + lcol);
        float4 g0 = *reinterpret_cast<const float4*>(Bm + (size_t)lrow        * w + kk + lcol);
        float4 g1 = *reinterpret_cast<const float4*>(Bm + (size_t)(lrow + 32) * w + kk + lcol);

        __syncthreads();   // previous iteration's readers done

        As[(lcol + 0) * LDSS + lrow]      = a0.x;
        As[(lcol + 1) * LDSS + lrow]      = a0.y;
        As[(lcol + 2) * LDSS + lrow]      = a0.z;
        As[(lcol + 3) * LDSS + lrow]      = a0.w;
        As[(lcol + 0) * LDSS + lrow + 32] = a1.x;
        As[(lcol + 1) * LDSS + lrow + 32] = a1.y;
        As[(lcol + 2) * LDSS + lrow + 32] = a1.z;
        As[(lcol + 3) * LDSS + lrow + 32] = a1.w;

        Bs[(lcol + 0) * LDSS + lrow]      = g0.x;
        Bs[(lcol + 1) * LDSS + lrow]      = g0.y;
        Bs[(lcol + 2) * LDSS + lrow]      = g0.z;
        Bs[(lcol + 3) * LDSS + lrow]      = g0.w;
        Bs[(lcol + 0) * LDSS + lrow + 32] = g1.x;
        Bs[(lcol + 1) * LDSS + lrow + 32] = g1.y;
        Bs[(lcol + 2) * LDSS + lrow + 32] = g1.z;
        Bs[(lcol + 3) * LDSS + lrow + 32] = g1.w;

        __syncthreads();

#pragma unroll
        for (int k = 0; k < BK; k++) {
            float4 av = *reinterpret_cast<const float4*>(&As[k * LDSS + tm]);
            float4 bv = *reinterpret_cast<const float4*>(&Bs[k * LDSS + tn]);
            float am[4] = {av.x, av.y, av.z, av.w};
            float bn[4] = {bv.x, bv.y, bv.z, bv.w};
#pragma unroll
            for (int i = 0; i < 4; i++)
#pragma unroll
                for (int j = 0; j < 4; j++) acc[i][j] = fmaf(am[i], bn[j], acc[i][j]);
        }
    }

    float4 bias = *reinterpret_cast<const float4*>(bp + n0 + tn);
#pragma unroll
    for (int i = 0; i < 4; i++) {
        int s = m0 + tm + i;
        float4 r;
        if (s < nv) {
            r = make_float4(acc[i][0] + bias.x, acc[i][1] + bias.y,
                            acc[i][2] + bias.z, acc[i][3] + bias.w);
        } else {
            r = make_float4(0.f, 0.f, 0.f, 0.f);
        }
        *reinterpret_cast<float4*>(outb + (size_t)s * kE + n0 + tn) = r;
    }
}

// ---------------------------------------------------------------------------
extern "C" void kernel_launch(void* const* d_in, const int* in_sizes, int n_in,
                              void* d_out, int out_size)
{
    const float* signal = (const float*)d_in[0];
    const int*   mask   = (const int*)d_in[1];
    const int*   bidx   = (const int*)d_in[2];
    const float* W0 = (const float*)d_in[3];
    const float* b0 = (const float*)d_in[4];
    const float* W1 = (const float*)d_in[5];
    const float* b1 = (const float*)d_in[6];
    const float* W2 = (const float*)d_in[7];
    const float* b2 = (const float*)d_in[8];
    float* out = (float*)d_out;

    int write_mask = (out_size > kB * kSmax * kE) ? 1 : 0;

    len_mask_kernel<<<kB, 256>>>(mask, bidx, out, write_mask);

    dim3 grid(kE / BN, kSmax / BM, kB);
    branch_gemm_kernel<<<grid, 256>>>(signal, bidx, W0, b0, W1, b1, W2, b2, out);
}

// round 4
// speedup vs baseline: 1.7503x; 1.7503x over previous
#include <cuda_runtime.h>
#include <cuda_bf16.h>
#include <cstdint>
#include <cstddef>

namespace {
constexpr int kB    = 128;
constexpr int kT    = 65536;
constexpr int kE    = 512;
constexpr int kSmax = 512;

constexpr int BM = 128;     // token rows per CTA
constexpr int BN = 128;     // embed cols per CTA
constexpr int KC = 64;      // K chunk in elements

constexpr int LDS  = 72;    // smem row stride in bf16 elems (144B, 16B-aligned, ldmatrix conflict-free)
constexpr int ROWB = LDS * 2;  // 144 bytes per row

// smem byte offsets
constexpr int OFF_AHI = 0;
constexpr int OFF_ALO = OFF_AHI + BM * ROWB;     // 18432
constexpr int OFF_BHI = OFF_ALO + BM * ROWB;     // 36864
constexpr int OFF_BLO = OFF_BHI + BN * ROWB;     // 55296
constexpr int SMEM_BYTES = OFF_BLO + BN * ROWB;  // 73728
}

__device__ int g_nvalid[kB];

// ---------------------------------------------------------------------------
// PTX helpers (base-target-safe: ldmatrix + mma.sync only)
// ---------------------------------------------------------------------------
__device__ __forceinline__ uint32_t smem_u32(const void* p) {
    uint32_t a;
    asm("{ .reg .u64 t; cvta.to.shared.u64 t, %1; cvt.u32.u64 %0, t; }" : "=r"(a) : "l"(p));
    return a;
}

__device__ __forceinline__ void ldsm_x4(uint32_t& r0, uint32_t& r1, uint32_t& r2,
                                        uint32_t& r3, uint32_t addr) {
    asm volatile("ldmatrix.sync.aligned.m8n8.x4.shared.b16 {%0,%1,%2,%3}, [%4];"
                 : "=r"(r0), "=r"(r1), "=r"(r2), "=r"(r3) : "r"(addr));
}

__device__ __forceinline__ void mma_bf16(float* c, const uint32_t* a, const uint32_t* b) {
    asm volatile(
        "mma.sync.aligned.m16n8k16.row.col.f32.bf16.bf16.f32 "
        "{%0,%1,%2,%3}, {%4,%5,%6,%7}, {%8,%9}, {%0,%1,%2,%3};"
        : "+f"(c[0]), "+f"(c[1]), "+f"(c[2]), "+f"(c[3])
        : "r"(a[0]), "r"(a[1]), "r"(a[2]), "r"(a[3]), "r"(b[0]), "r"(b[1]));
}

// bf16 split: x = hi + lo (+ ~2^-18 residual)
__device__ __forceinline__ void split_pack(float x, float y, uint32_t& hi, uint32_t& lo) {
    __nv_bfloat16 hx = __float2bfloat16(x);
    __nv_bfloat16 hy = __float2bfloat16(y);
    __nv_bfloat16 lx = __float2bfloat16(x - __bfloat162float(hx));
    __nv_bfloat16 ly = __float2bfloat16(y - __bfloat162float(hy));
    __nv_bfloat162 h; h.x = hx; h.y = hy;
    __nv_bfloat162 l; l.x = lx; l.y = ly;
    hi = *reinterpret_cast<uint32_t*>(&h);
    lo = *reinterpret_cast<uint32_t*>(&l);
}

// ---------------------------------------------------------------------------
// Kernel A: per-sample mask popcount -> n_valid, plus padding_mask output.
// ---------------------------------------------------------------------------
__global__ __launch_bounds__(256) void len_mask_kernel(
    const int* __restrict__ mask,
    const int* __restrict__ branch_idx,
    float* __restrict__ out,
    int write_mask)
{
    int b = blockIdx.x;
    int t = threadIdx.x;

    const uint4* p = reinterpret_cast<const uint4*>(mask + (size_t)b * kT);
    int sum = 0;
#pragma unroll 4
    for (int i = t; i < kT / 4; i += 256) {
        uint4 v = p[i];
        sum += (int)((v.x & 1u) + (v.y & 1u) + (v.z & 1u) + (v.w & 1u));
    }
#pragma unroll
    for (int o = 16; o > 0; o >>= 1) sum += __shfl_down_sync(0xffffffffu, sum, o);

    __shared__ int warp_sums[8];
    __shared__ int nv_sh;
    if ((t & 31) == 0) warp_sums[t >> 5] = sum;
    __syncthreads();
    if (t == 0) {
        int tot = 0;
#pragma unroll
        for (int i = 0; i < 8; i++) tot += warp_sums[i];
        int bi = branch_idx[b];
        int w  = 128 << bi;
        int Sb = kT / w;
        int nv = tot / w;
        if (nv > Sb) nv = Sb;
        g_nvalid[b] = nv;
        nv_sh = nv;
    }
    __syncthreads();

    if (write_mask) {
        int nv = nv_sh;
        float* mout = out + (size_t)kB * kSmax * kE + (size_t)b * kSmax;
        for (int s = t; s < kSmax; s += 256) mout[s] = (s < nv) ? 1.0f : 0.0f;
    }
}

// ---------------------------------------------------------------------------
// Kernel B: bf16-split tensor-core GEMM via mma.sync.
// Grid (kE/BN=4, kSmax/BM=4, kB). 256 threads = 8 warps as 4(m) x 2(n).
// ---------------------------------------------------------------------------
__global__ __launch_bounds__(256, 1) void branch_gemm_mma(
    const float* __restrict__ signal,
    const int*   __restrict__ branch_idx,
    const float* __restrict__ W0, const float* __restrict__ b0,
    const float* __restrict__ W1, const float* __restrict__ b1,
    const float* __restrict__ W2, const float* __restrict__ b2,
    float* __restrict__ out)
{
    extern __shared__ char smem[];
    const int tid  = threadIdx.x;
    const int b    = blockIdx.z;
    const int m0   = blockIdx.y * BM;
    const int n0   = blockIdx.x * BN;

    float* outb = out + (size_t)b * kSmax * kE;
    const int nv = g_nvalid[b];

    if (m0 >= nv) {
        float4 z = make_float4(0.f, 0.f, 0.f, 0.f);
#pragma unroll
        for (int i = 0; i < 16; i++) {
            int u   = tid + i * 256;          // 4096 float4 units = 128x128 floats
            int row = u >> 5;
            int c4  = (u & 31) << 2;
            *reinterpret_cast<float4*>(outb + (size_t)(m0 + row) * kE + n0 + c4) = z;
        }
        return;
    }

    const int bi   = branch_idx[b];
    const int logw = 7 + bi;
    const int nchunks = (1 << logw) / KC;     // 2, 4 or 8
    const float* Wp = (bi == 0) ? W0 : (bi == 1) ? W1 : W2;
    const float* bp = (bi == 0) ? b0 : (bi == 1) ? b1 : b2;
    const float* Asrc = signal + (size_t)b * kT + ((size_t)m0 << logw);
    const float* Bsrc = Wp + ((size_t)n0 << logw);

    const uint32_t sbase = smem_u32(smem);
    const int lane   = tid & 31;
    const int warp   = tid >> 5;
    const int warp_m = warp & 3;        // 0..3 -> m offset *32
    const int warp_n = warp >> 2;       // 0..1 -> n offset *64

    // ldmatrix lane address templates (byte offsets into the tiles)
    const int a_row = warp_m * 32 + (lane & 7) + ((lane >> 3) & 1) * 8;
    const int a_col = ((lane >> 4) & 1) * 8;
    const uint32_t aHiAddr = sbase + OFF_AHI + a_row * ROWB + a_col * 2;
    const uint32_t aLoAddr = sbase + OFF_ALO + a_row * ROWB + a_col * 2;
    const int b_row = warp_n * 64 + (lane & 7) + ((lane >> 4) & 1) * 8;
    const int b_col = ((lane >> 3) & 1) * 8;
    const uint32_t bHiAddr = sbase + OFF_BHI + b_row * ROWB + b_col * 2;
    const uint32_t bLoAddr = sbase + OFF_BLO + b_row * ROWB + b_col * 2;

    // per-thread smem store offset pieces: u = tid + i*256 -> row=u>>4, c4=(u&15)*4
    float acc[2][8][4];
#pragma unroll
    for (int mi = 0; mi < 2; mi++)
#pragma unroll
        for (int nj = 0; nj < 8; nj++)
#pragma unroll
            for (int q = 0; q < 4; q++) acc[mi][nj][q] = 0.f;

    float4 av[8], bv[8];
    // preload chunk 0
#pragma unroll
    for (int i = 0; i < 8; i++) {
        int u = tid + i * 256;
        int row = u >> 4, c4 = (u & 15) << 2;
        av[i] = *reinterpret_cast<const float4*>(Asrc + ((size_t)row << logw) + c4);
        bv[i] = *reinterpret_cast<const float4*>(Bsrc + ((size_t)row << logw) + c4);
    }

    for (int c = 0; ; ) {
        if (c) __syncthreads();
        // split + store to smem
#pragma unroll
        for (int i = 0; i < 8; i++) {
            int u = tid + i * 256;
            int row = u >> 4, c4 = (u & 15) << 2;
            uint32_t off = row * ROWB + c4 * 2;
            uint32_t h01, l01, h23, l23;
            split_pack(av[i].x, av[i].y, h01, l01);
            split_pack(av[i].z, av[i].w, h23, l23);
            *reinterpret_cast<uint2*>(smem + OFF_AHI + off) = make_uint2(h01, h23);
            *reinterpret_cast<uint2*>(smem + OFF_ALO + off) = make_uint2(l01, l23);
            split_pack(bv[i].x, bv[i].y, h01, l01);
            split_pack(bv[i].z, bv[i].w, h23, l23);
            *reinterpret_cast<uint2*>(smem + OFF_BHI + off) = make_uint2(h01, h23);
            *reinterpret_cast<uint2*>(smem + OFF_BLO + off) = make_uint2(l01, l23);
        }
        __syncthreads();

        const bool more = (c + 1 < nchunks);
        if (more) {
            const int kk = (c + 1) * KC;
#pragma unroll
            for (int i = 0; i < 8; i++) {
                int u = tid + i * 256;
                int row = u >> 4, c4 = (u & 15) << 2;
                av[i] = *reinterpret_cast<const float4*>(Asrc + ((size_t)row << logw) + kk + c4);
                bv[i] = *reinterpret_cast<const float4*>(Bsrc + ((size_t)row << logw) + kk + c4);
            }
        }

        // compute: 4 k16 steps over this KC=64 chunk
#pragma unroll
        for (int k16 = 0; k16 < 4; k16++) {
            const uint32_t kb = k16 * 32;   // 16 elems * 2B
            uint32_t ah[2][4], al[2][4];
            ldsm_x4(ah[0][0], ah[0][1], ah[0][2], ah[0][3], aHiAddr + kb);
            ldsm_x4(ah[1][0], ah[1][1], ah[1][2], ah[1][3], aHiAddr + 16 * ROWB + kb);
            ldsm_x4(al[0][0], al[0][1], al[0][2], al[0][3], aLoAddr + kb);
            ldsm_x4(al[1][0], al[1][1], al[1][2], al[1][3], aLoAddr + 16 * ROWB + kb);
            uint32_t bh[8][2], bl[8][2];
#pragma unroll
            for (int q = 0; q < 4; q++) {
                uint32_t r0, r1, r2, r3;
                ldsm_x4(r0, r1, r2, r3, bHiAddr + q * 16 * ROWB + kb);
                bh[2 * q][0] = r0; bh[2 * q][1] = r1;
                bh[2 * q + 1][0] = r2; bh[2 * q + 1][1] = r3;
                ldsm_x4(r0, r1, r2, r3, bLoAddr + q * 16 * ROWB + kb);
                bl[2 * q][0] = r0; bl[2 * q][1] = r1;
                bl[2 * q + 1][0] = r2; bl[2 * q + 1][1] = r3;
            }
#pragma unroll
            for (int mi = 0; mi < 2; mi++)
#pragma unroll
                for (int nj = 0; nj < 8; nj++) {
                    mma_bf16(acc[mi][nj], ah[mi], bh[nj]);
                    mma_bf16(acc[mi][nj], al[mi], bh[nj]);
                    mma_bf16(acc[mi][nj], ah[mi], bl[nj]);
                }
        }

        if (!more) break;
        c++;
    }

    // Epilogue: fragments -> gmem with bias + n_valid predicate.
    const int col0 = (lane & 3) * 2;
    const int rbase = m0 + warp_m * 32 + (lane >> 2);
    const int ncol  = n0 + warp_n * 64;
#pragma unroll
    for (int mi = 0; mi < 2; mi++) {
        int r0 = rbase + mi * 16;
        int r1 = r0 + 8;
        bool v0 = r0 < nv, v1 = r1 < nv;
        float* o0p = outb + (size_t)r0 * kE + ncol + col0;
        float* o1p = outb + (size_t)r1 * kE + ncol + col0;
#pragma unroll
        for (int nj = 0; nj < 8; nj++) {
            float2 bias = *reinterpret_cast<const float2*>(bp + ncol + nj * 8 + col0);
            float2 o0 = v0 ? make_float2(acc[mi][nj][0] + bias.x, acc[mi][nj][1] + bias.y)
                           : make_float2(0.f, 0.f);
            float2 o1 = v1 ? make_float2(acc[mi][nj][2] + bias.x, acc[mi][nj][3] + bias.y)
                           : make_float2(0.f, 0.f);
            *reinterpret_cast<float2*>(o0p + nj * 8) = o0;
            *reinterpret_cast<float2*>(o1p + nj * 8) = o1;
        }
    }
}

// ---------------------------------------------------------------------------
extern "C" void kernel_launch(void* const* d_in, const int* in_sizes, int n_in,
                              void* d_out, int out_size)
{
    const float* signal = (const float*)d_in[0];
    const int*   mask   = (const int*)d_in[1];
    const int*   bidx   = (const int*)d_in[2];
    const float* W0 = (const float*)d_in[3];
    const float* b0 = (const float*)d_in[4];
    const float* W1 = (const float*)d_in[5];
    const float* b1 = (const float*)d_in[6];
    const float* W2 = (const float*)d_in[7];
    const float* b2 = (const float*)d_in[8];
    float* out = (float*)d_out;

    int write_mask = (out_size > kB * kSmax * kE) ? 1 : 0;

    len_mask_kernel<<<kB, 256>>>(mask, bidx, out, write_mask);

    static bool attr_set = false;
    if (!attr_set) {
        cudaFuncSetAttribute(branch_gemm_mma,
                             cudaFuncAttributeMaxDynamicSharedMemorySize, SMEM_BYTES);
        attr_set = true;
    }
    dim3 grid(kE / BN, kSmax / BM, kB);
    branch_gemm_mma<<<grid, 256, SMEM_BYTES>>>(signal, bidx, W0, b0, W1, b1, W2, b2, out);
}

// round 5
// speedup vs baseline: 1.8398x; 1.0512x over previous
#include <cuda_runtime.h>
#include <cuda_bf16.h>
#include <cstdint>
#include <cstddef>

namespace {
constexpr int kB    = 128;
constexpr int kT    = 65536;
constexpr int kE    = 512;
constexpr int kSmax = 512;

constexpr int BM = 128;     // token rows per CTA
constexpr int BN = 128;     // embed cols per CTA
constexpr int KC = 64;      // K chunk in elements

constexpr int LDS  = 72;    // smem row stride in bf16 elems
constexpr int ROWB = LDS * 2;  // 144 bytes per row

// per-buffer byte offsets
constexpr int OFF_AHI = 0;
constexpr int OFF_ALO = OFF_AHI + BM * ROWB;     // 18432
constexpr int OFF_BHI = OFF_ALO + BM * ROWB;     // 36864
constexpr int OFF_BLO = OFF_BHI + BN * ROWB;     // 55296
constexpr int BUF_STRIDE = OFF_BLO + BN * ROWB;  // 73728
constexpr int SMEM_BYTES = 2 * BUF_STRIDE;       // 147456
}

__device__ int g_nvalid[kB];
__device__ int g_cnt[kB];
__device__ int g_done[kB];

// ---------------------------------------------------------------------------
__device__ __forceinline__ uint32_t smem_u32(const void* p) {
    uint32_t a;
    asm("{ .reg .u64 t; cvta.to.shared.u64 t, %1; cvt.u32.u64 %0, t; }" : "=r"(a) : "l"(p));
    return a;
}

__device__ __forceinline__ void ldsm_x4(uint32_t& r0, uint32_t& r1, uint32_t& r2,
                                        uint32_t& r3, uint32_t addr) {
    asm volatile("ldmatrix.sync.aligned.m8n8.x4.shared.b16 {%0,%1,%2,%3}, [%4];"
                 : "=r"(r0), "=r"(r1), "=r"(r2), "=r"(r3) : "r"(addr));
}

__device__ __forceinline__ void mma_bf16(float* c, const uint32_t* a, const uint32_t* b) {
    asm volatile(
        "mma.sync.aligned.m16n8k16.row.col.f32.bf16.bf16.f32 "
        "{%0,%1,%2,%3}, {%4,%5,%6,%7}, {%8,%9}, {%0,%1,%2,%3};"
        : "+f"(c[0]), "+f"(c[1]), "+f"(c[2]), "+f"(c[3])
        : "r"(a[0]), "r"(a[1]), "r"(a[2]), "r"(a[3]), "r"(b[0]), "r"(b[1]));
}

__device__ __forceinline__ void split_pack(float x, float y, uint32_t& hi, uint32_t& lo) {
    __nv_bfloat16 hx = __float2bfloat16(x);
    __nv_bfloat16 hy = __float2bfloat16(y);
    __nv_bfloat16 lx = __float2bfloat16(x - __bfloat162float(hx));
    __nv_bfloat16 ly = __float2bfloat16(y - __bfloat162float(hy));
    __nv_bfloat162 h; h.x = hx; h.y = hy;
    __nv_bfloat162 l; l.x = lx; l.y = ly;
    hi = *reinterpret_cast<uint32_t*>(&h);
    lo = *reinterpret_cast<uint32_t*>(&l);
}

// ---------------------------------------------------------------------------
// Kernel A: 4 blocks per sample popcount with atomic reduce; last block
// finalizes n_valid + padding mask and resets counters (graph-replay safe).
// ---------------------------------------------------------------------------
__global__ __launch_bounds__(256) void len_mask_kernel(
    const int* __restrict__ mask,
    const int* __restrict__ branch_idx,
    float* __restrict__ out,
    int write_mask)
{
    const int b = blockIdx.x >> 2;
    const int q = blockIdx.x & 3;
    const int t = threadIdx.x;

    // quarter q of sample b: kT/4 = 16384 ints = 4096 uint4
    const uint4* p = reinterpret_cast<const uint4*>(mask + (size_t)b * kT) + q * 4096;
    int sum = 0;
#pragma unroll 4
    for (int i = t; i < 4096; i += 256) {
        uint4 v = p[i];
        sum += (int)((v.x & 1u) + (v.y & 1u) + (v.z & 1u) + (v.w & 1u));
    }
#pragma unroll
    for (int o = 16; o > 0; o >>= 1) sum += __shfl_down_sync(0xffffffffu, sum, o);

    __shared__ int warp_sums[8];
    __shared__ int is_last;
    if ((t & 31) == 0) warp_sums[t >> 5] = sum;
    __syncthreads();
    if (t == 0) {
        int tot = 0;
#pragma unroll
        for (int i = 0; i < 8; i++) tot += warp_sums[i];
        atomicAdd(&g_cnt[b], tot);
        __threadfence();
        int old = atomicAdd(&g_done[b], 1);
        is_last = (old == 3);
    }
    __syncthreads();

    if (!is_last) return;

    __shared__ int nv_sh;
    if (t == 0) {
        __threadfence();
        int tot = atomicAdd(&g_cnt[b], 0);
        int bi = branch_idx[b];
        int w  = 128 << bi;
        int Sb = kT / w;
        int nv = tot / w;
        if (nv > Sb) nv = Sb;
        g_nvalid[b] = nv;
        nv_sh = nv;
        g_cnt[b]  = 0;      // reset for next graph replay
        g_done[b] = 0;
    }
    __syncthreads();

    if (write_mask) {
        int nv = nv_sh;
        float* mout = out + (size_t)kB * kSmax * kE + (size_t)b * kSmax;
        for (int s = t; s < kSmax; s += 256) mout[s] = (s < nv) ? 1.0f : 0.0f;
    }
}

// ---------------------------------------------------------------------------
// Kernel B: bf16-split tensor-core GEMM, double-buffered software pipeline.
// Grid (4, 4, 128). 256 threads = 8 warps as 4(m) x 2(n), warp tile 32x64.
// ---------------------------------------------------------------------------
__global__ __launch_bounds__(256, 1) void branch_gemm_mma(
    const float* __restrict__ signal,
    const int*   __restrict__ branch_idx,
    const float* __restrict__ W0, const float* __restrict__ b0,
    const float* __restrict__ W1, const float* __restrict__ b1,
    const float* __restrict__ W2, const float* __restrict__ b2,
    float* __restrict__ out)
{
    extern __shared__ char smem[];
    const int tid  = threadIdx.x;
    const int b    = blockIdx.z;
    const int m0   = blockIdx.y * BM;
    const int n0   = blockIdx.x * BN;

    float* outb = out + (size_t)b * kSmax * kE;
    const int nv = g_nvalid[b];

    if (m0 >= nv) {
        float4 z = make_float4(0.f, 0.f, 0.f, 0.f);
#pragma unroll
        for (int i = 0; i < 16; i++) {
            int u   = tid + i * 256;
            int row = u >> 5;
            int c4  = (u & 31) << 2;
            *reinterpret_cast<float4*>(outb + (size_t)(m0 + row) * kE + n0 + c4) = z;
        }
        return;
    }

    const int bi   = branch_idx[b];
    const int logw = 7 + bi;
    const int nchunks = (1 << logw) / KC;     // 2, 4 or 8
    const float* Wp = (bi == 0) ? W0 : (bi == 1) ? W1 : W2;
    const float* bp = (bi == 0) ? b0 : (bi == 1) ? b1 : b2;
    const float* Asrc = signal + (size_t)b * kT + ((size_t)m0 << logw);
    const float* Bsrc = Wp + ((size_t)n0 << logw);

    const uint32_t sbase = smem_u32(smem);
    const int lane   = tid & 31;
    const int warp   = tid >> 5;
    const int warp_m = warp & 3;
    const int warp_n = warp >> 2;

    const int a_row = warp_m * 32 + (lane & 7) + ((lane >> 3) & 1) * 8;
    const int a_col = ((lane >> 4) & 1) * 8;
    const uint32_t aHi0 = sbase + OFF_AHI + a_row * ROWB + a_col * 2;
    const uint32_t aLo0 = sbase + OFF_ALO + a_row * ROWB + a_col * 2;
    const int b_row = warp_n * 64 + (lane & 7) + ((lane >> 4) & 1) * 8;
    const int b_col = ((lane >> 3) & 1) * 8;
    const uint32_t bHi0 = sbase + OFF_BHI + b_row * ROWB + b_col * 2;
    const uint32_t bLo0 = sbase + OFF_BLO + b_row * ROWB + b_col * 2;

    float acc[2][8][4];
#pragma unroll
    for (int mi = 0; mi < 2; mi++)
#pragma unroll
        for (int nj = 0; nj < 8; nj++)
#pragma unroll
            for (int q = 0; q < 4; q++) acc[mi][nj][q] = 0.f;

    // thread's store slot: u = tid + i*256 -> row = u>>4, c4 = (u&15)*4
    const int srow = tid >> 4;          // base row for i=0 (rows advance by 16 per i)
    const int sc4  = (tid & 15) << 2;
    const uint32_t soff = srow * ROWB + sc4 * 2;

    float4 av[8], bv[8];
    // prologue: load + split chunk 0 into buffer 0
#pragma unroll
    for (int i = 0; i < 8; i++) {
        int row = srow + i * 16;
        av[i] = *reinterpret_cast<const float4*>(Asrc + ((size_t)row << logw) + sc4);
        bv[i] = *reinterpret_cast<const float4*>(Bsrc + ((size_t)row << logw) + sc4);
    }
#pragma unroll
    for (int i = 0; i < 8; i++) {
        uint32_t off = soff + i * 16 * ROWB;
        uint32_t h01, l01, h23, l23;
        split_pack(av[i].x, av[i].y, h01, l01);
        split_pack(av[i].z, av[i].w, h23, l23);
        *reinterpret_cast<uint2*>(smem + OFF_AHI + off) = make_uint2(h01, h23);
        *reinterpret_cast<uint2*>(smem + OFF_ALO + off) = make_uint2(l01, l23);
        split_pack(bv[i].x, bv[i].y, h01, l01);
        split_pack(bv[i].z, bv[i].w, h23, l23);
        *reinterpret_cast<uint2*>(smem + OFF_BHI + off) = make_uint2(h01, h23);
        *reinterpret_cast<uint2*>(smem + OFF_BLO + off) = make_uint2(l01, l23);
    }
    __syncthreads();

    for (int c = 0; c < nchunks; c++) {
        const int bufoff = (c & 1) * BUF_STRIDE;
        const bool more = (c + 1 < nchunks);

        // issue next chunk's gmem loads early (hide DRAM latency under MMA)
        if (more) {
            const int kk = (c + 1) * KC;
#pragma unroll
            for (int i = 0; i < 8; i++) {
                int row = srow + i * 16;
                av[i] = *reinterpret_cast<const float4*>(Asrc + ((size_t)row << logw) + kk + sc4);
                bv[i] = *reinterpret_cast<const float4*>(Bsrc + ((size_t)row << logw) + kk + sc4);
            }
        }

        // compute chunk c from buffer c&1
#pragma unroll
        for (int k16 = 0; k16 < 4; k16++) {
            const uint32_t kb = bufoff + k16 * 32;
            uint32_t ah[2][4], al[2][4];
            ldsm_x4(ah[0][0], ah[0][1], ah[0][2], ah[0][3], aHi0 + kb);
            ldsm_x4(ah[1][0], ah[1][1], ah[1][2], ah[1][3], aHi0 + 16 * ROWB + kb);
            ldsm_x4(al[0][0], al[0][1], al[0][2], al[0][3], aLo0 + kb);
            ldsm_x4(al[1][0], al[1][1], al[1][2], al[1][3], aLo0 + 16 * ROWB + kb);
            uint32_t bh[8][2], bl[8][2];
#pragma unroll
            for (int q = 0; q < 4; q++) {
                uint32_t r0, r1, r2, r3;
                ldsm_x4(r0, r1, r2, r3, bHi0 + q * 16 * ROWB + kb);
                bh[2 * q][0] = r0; bh[2 * q][1] = r1;
                bh[2 * q + 1][0] = r2; bh[2 * q + 1][1] = r3;
                ldsm_x4(r0, r1, r2, r3, bLo0 + q * 16 * ROWB + kb);
                bl[2 * q][0] = r0; bl[2 * q][1] = r1;
                bl[2 * q + 1][0] = r2; bl[2 * q + 1][1] = r3;
            }
#pragma unroll
            for (int mi = 0; mi < 2; mi++)
#pragma unroll
                for (int nj = 0; nj < 8; nj++) {
                    mma_bf16(acc[mi][nj], ah[mi], bh[nj]);
                    mma_bf16(acc[mi][nj], al[mi], bh[nj]);
                    mma_bf16(acc[mi][nj], ah[mi], bl[nj]);
                }
        }

        // split + store chunk c+1 into the other buffer
        if (more) {
            const int obuf = ((c + 1) & 1) * BUF_STRIDE;
#pragma unroll
            for (int i = 0; i < 8; i++) {
                uint32_t off = obuf + soff + i * 16 * ROWB;
                uint32_t h01, l01, h23, l23;
                split_pack(av[i].x, av[i].y, h01, l01);
                split_pack(av[i].z, av[i].w, h23, l23);
                *reinterpret_cast<uint2*>(smem + OFF_AHI + off) = make_uint2(h01, h23);
                *reinterpret_cast<uint2*>(smem + OFF_ALO + off) = make_uint2(l01, l23);
                split_pack(bv[i].x, bv[i].y, h01, l01);
                split_pack(bv[i].z, bv[i].w, h23, l23);
                *reinterpret_cast<uint2*>(smem + OFF_BHI + off) = make_uint2(h01, h23);
                *reinterpret_cast<uint2*>(smem + OFF_BLO + off) = make_uint2(l01, l23);
            }
            __syncthreads();
        }
    }

    // Epilogue: fragments -> gmem with bias + n_valid predicate.
    const int col0 = (lane & 3) * 2;
    const int rbase = m0 + warp_m * 32 + (lane >> 2);
    const int ncol  = n0 + warp_n * 64;
#pragma unroll
    for (int mi = 0; mi < 2; mi++) {
        int r0 = rbase + mi * 16;
        int r1 = r0 + 8;
        bool v0 = r0 < nv, v1 = r1 < nv;
        float* o0p = outb + (size_t)r0 * kE + ncol + col0;
        float* o1p = outb + (size_t)r1 * kE + ncol + col0;
#pragma unroll
        for (int nj = 0; nj < 8; nj++) {
            float2 bias = *reinterpret_cast<const float2*>(bp + ncol + nj * 8 + col0);
            float2 o0 = v0 ? make_float2(acc[mi][nj][0] + bias.x, acc[mi][nj][1] + bias.y)
                           : make_float2(0.f, 0.f);
            float2 o1 = v1 ? make_float2(acc[mi][nj][2] + bias.x, acc[mi][nj][3] + bias.y)
                           : make_float2(0.f, 0.f);
            *reinterpret_cast<float2*>(o0p + nj * 8) = o0;
            *reinterpret_cast<float2*>(o1p + nj * 8) = o1;
        }
    }
}

// ---------------------------------------------------------------------------
extern "C" void kernel_launch(void* const* d_in, const int* in_sizes, int n_in,
                              void* d_out, int out_size)
{
    const float* signal = (const float*)d_in[0];
    const int*   mask   = (const int*)d_in[1];
    const int*   bidx   = (const int*)d_in[2];
    const float* W0 = (const float*)d_in[3];
    const float* b0 = (const float*)d_in[4];
    const float* W1 = (const float*)d_in[5];
    const float* b1 = (const float*)d_in[6];
    const float* W2 = (const float*)d_in[7];
    const float* b2 = (const float*)d_in[8];
    float* out = (float*)d_out;

    int write_mask = (out_size > kB * kSmax * kE) ? 1 : 0;

    len_mask_kernel<<<kB * 4, 256>>>(mask, bidx, out, write_mask);

    static bool attr_set = false;
    if (!attr_set) {
        cudaFuncSetAttribute(branch_gemm_mma,
                             cudaFuncAttributeMaxDynamicSharedMemorySize, SMEM_BYTES);
        attr_set = true;
    }
    dim3 grid(kE / BN, kSmax / BM, kB);
    branch_gemm_mma<<<grid, 256, SMEM_BYTES>>>(signal, bidx, W0, b0, W1, b1, W2, b2, out);
}

// round 6
// speedup vs baseline: 1.9443x; 1.0568x over previous
#include <cuda_runtime.h>
#include <cuda_bf16.h>
#include <cstdint>
#include <cstddef>

namespace {
constexpr int kB    = 128;
constexpr int kT    = 65536;
constexpr int kE    = 512;
constexpr int kSmax = 512;

constexpr int BM = 128;
constexpr int BN = 128;
constexpr int KC = 64;

constexpr int NTHREADS = 512;       // 16 warps: 4(m) x 4(n)

constexpr int LDS  = 72;
constexpr int ROWB = LDS * 2;       // 144 bytes/row

constexpr int OFF_AHI = 0;
constexpr int OFF_ALO = OFF_AHI + BM * ROWB;
constexpr int OFF_BHI = OFF_ALO + BM * ROWB;
constexpr int OFF_BLO = OFF_BHI + BN * ROWB;
constexpr int BUF_STRIDE = OFF_BLO + BN * ROWB;   // 73728
constexpr int SMEM_BYTES = 2 * BUF_STRIDE;        // 147456
}

__device__ int g_nvalid[kB];
__device__ int g_cnt[kB];
__device__ int g_done[kB];

// ---------------------------------------------------------------------------
__device__ __forceinline__ uint32_t smem_u32(const void* p) {
    uint32_t a;
    asm("{ .reg .u64 t; cvta.to.shared.u64 t, %1; cvt.u32.u64 %0, t; }" : "=r"(a) : "l"(p));
    return a;
}

__device__ __forceinline__ void ldsm_x4(uint32_t& r0, uint32_t& r1, uint32_t& r2,
                                        uint32_t& r3, uint32_t addr) {
    asm volatile("ldmatrix.sync.aligned.m8n8.x4.shared.b16 {%0,%1,%2,%3}, [%4];"
                 : "=r"(r0), "=r"(r1), "=r"(r2), "=r"(r3) : "r"(addr));
}

__device__ __forceinline__ void mma_bf16(float* c, const uint32_t* a, const uint32_t* b) {
    asm volatile(
        "mma.sync.aligned.m16n8k16.row.col.f32.bf16.bf16.f32 "
        "{%0,%1,%2,%3}, {%4,%5,%6,%7}, {%8,%9}, {%0,%1,%2,%3};"
        : "+f"(c[0]), "+f"(c[1]), "+f"(c[2]), "+f"(c[3])
        : "r"(a[0]), "r"(a[1]), "r"(a[2]), "r"(a[3]), "r"(b[0]), "r"(b[1]));
}

__device__ __forceinline__ void split_pack(float x, float y, uint32_t& hi, uint32_t& lo) {
    __nv_bfloat16 hx = __float2bfloat16(x);
    __nv_bfloat16 hy = __float2bfloat16(y);
    __nv_bfloat16 lx = __float2bfloat16(x - __bfloat162float(hx));
    __nv_bfloat16 ly = __float2bfloat16(y - __bfloat162float(hy));
    __nv_bfloat162 h; h.x = hx; h.y = hy;
    __nv_bfloat162 l; l.x = lx; l.y = ly;
    hi = *reinterpret_cast<uint32_t*>(&h);
    lo = *reinterpret_cast<uint32_t*>(&l);
}

// ---------------------------------------------------------------------------
// Kernel A: 8 blocks/sample popcount, atomic reduce; last block finalizes.
// ---------------------------------------------------------------------------
__global__ __launch_bounds__(256) void len_mask_kernel(
    const int* __restrict__ mask,
    const int* __restrict__ branch_idx,
    float* __restrict__ out,
    int write_mask)
{
    const int b = blockIdx.x >> 3;
    const int q = blockIdx.x & 7;
    const int t = threadIdx.x;

    const uint4* p = reinterpret_cast<const uint4*>(mask + (size_t)b * kT) + q * 2048;
    int sum = 0;
#pragma unroll 4
    for (int i = t; i < 2048; i += 256) {
        uint4 v = p[i];
        sum += (int)((v.x & 1u) + (v.y & 1u) + (v.z & 1u) + (v.w & 1u));
    }
#pragma unroll
    for (int o = 16; o > 0; o >>= 1) sum += __shfl_down_sync(0xffffffffu, sum, o);

    __shared__ int warp_sums[8];
    __shared__ int is_last;
    if ((t & 31) == 0) warp_sums[t >> 5] = sum;
    __syncthreads();
    if (t == 0) {
        int tot = 0;
#pragma unroll
        for (int i = 0; i < 8; i++) tot += warp_sums[i];
        atomicAdd(&g_cnt[b], tot);
        __threadfence();
        int old = atomicAdd(&g_done[b], 1);
        is_last = (old == 7);
    }
    __syncthreads();

    if (!is_last) return;

    __shared__ int nv_sh;
    if (t == 0) {
        __threadfence();
        int tot = atomicAdd(&g_cnt[b], 0);
        int bi = branch_idx[b];
        int w  = 128 << bi;
        int Sb = kT / w;
        int nv = tot / w;
        if (nv > Sb) nv = Sb;
        g_nvalid[b] = nv;
        nv_sh = nv;
        g_cnt[b]  = 0;
        g_done[b] = 0;
    }
    __syncthreads();

    if (write_mask) {
        int nv = nv_sh;
        float* mout = out + (size_t)kB * kSmax * kE + (size_t)b * kSmax;
        for (int s = t; s < kSmax; s += 256) mout[s] = (s < nv) ? 1.0f : 0.0f;
    }
}

// ---------------------------------------------------------------------------
// Kernel B: bf16-split mma.sync GEMM, 16 warps (4m x 4n), warp tile 32x32,
// double-buffered. Grid (4, 4, 128).
// ---------------------------------------------------------------------------
__global__ __launch_bounds__(NTHREADS, 1) void branch_gemm_mma(
    const float* __restrict__ signal,
    const int*   __restrict__ branch_idx,
    const float* __restrict__ W0, const float* __restrict__ b0,
    const float* __restrict__ W1, const float* __restrict__ b1,
    const float* __restrict__ W2, const float* __restrict__ b2,
    float* __restrict__ out)
{
    extern __shared__ char smem[];
    const int tid  = threadIdx.x;
    const int b    = blockIdx.z;
    const int m0   = blockIdx.y * BM;
    const int n0   = blockIdx.x * BN;

    float* outb = out + (size_t)b * kSmax * kE;
    const int nv = g_nvalid[b];

    if (m0 >= nv) {
        float4 z = make_float4(0.f, 0.f, 0.f, 0.f);
#pragma unroll
        for (int i = 0; i < 8; i++) {
            int u   = tid + i * NTHREADS;     // 4096 float4 units
            int row = u >> 5;
            int c4  = (u & 31) << 2;
            *reinterpret_cast<float4*>(outb + (size_t)(m0 + row) * kE + n0 + c4) = z;
        }
        return;
    }

    const int bi   = branch_idx[b];
    const int logw = 7 + bi;
    const int nchunks = (1 << logw) / KC;
    const float* Wp = (bi == 0) ? W0 : (bi == 1) ? W1 : W2;
    const float* bp = (bi == 0) ? b0 : (bi == 1) ? b1 : b2;
    const float* Asrc = signal + (size_t)b * kT + ((size_t)m0 << logw);
    const float* Bsrc = Wp + ((size_t)n0 << logw);

    const uint32_t sbase = smem_u32(smem);
    const int lane   = tid & 31;
    const int warp   = tid >> 5;
    const int warp_m = warp & 3;        // m offset *32
    const int warp_n = warp >> 2;       // n offset *32

    const int a_row = warp_m * 32 + (lane & 7) + ((lane >> 3) & 1) * 8;
    const int a_col = ((lane >> 4) & 1) * 8;
    const uint32_t aHi0 = sbase + OFF_AHI + a_row * ROWB + a_col * 2;
    const uint32_t aLo0 = sbase + OFF_ALO + a_row * ROWB + a_col * 2;
    const int b_row = warp_n * 32 + (lane & 7) + ((lane >> 4) & 1) * 8;
    const int b_col = ((lane >> 3) & 1) * 8;
    const uint32_t bHi0 = sbase + OFF_BHI + b_row * ROWB + b_col * 2;
    const uint32_t bLo0 = sbase + OFF_BLO + b_row * ROWB + b_col * 2;

    float acc[2][4][4];
#pragma unroll
    for (int mi = 0; mi < 2; mi++)
#pragma unroll
        for (int nj = 0; nj < 4; nj++)
#pragma unroll
            for (int q = 0; q < 4; q++) acc[mi][nj][q] = 0.f;

    // loader slot: u = tid + i*512 -> row = u>>4 (stride 32 per i), c4 = (u&15)*4
    const int srow = tid >> 4;
    const int sc4  = (tid & 15) << 2;
    const uint32_t soff = srow * ROWB + sc4 * 2;

    float4 av[4], bv[4];
#pragma unroll
    for (int i = 0; i < 4; i++) {
        int row = srow + i * 32;
        av[i] = *reinterpret_cast<const float4*>(Asrc + ((size_t)row << logw) + sc4);
        bv[i] = *reinterpret_cast<const float4*>(Bsrc + ((size_t)row << logw) + sc4);
    }
#pragma unroll
    for (int i = 0; i < 4; i++) {
        uint32_t off = soff + i * 32 * ROWB;
        uint32_t h01, l01, h23, l23;
        split_pack(av[i].x, av[i].y, h01, l01);
        split_pack(av[i].z, av[i].w, h23, l23);
        *reinterpret_cast<uint2*>(smem + OFF_AHI + off) = make_uint2(h01, h23);
        *reinterpret_cast<uint2*>(smem + OFF_ALO + off) = make_uint2(l01, l23);
        split_pack(bv[i].x, bv[i].y, h01, l01);
        split_pack(bv[i].z, bv[i].w, h23, l23);
        *reinterpret_cast<uint2*>(smem + OFF_BHI + off) = make_uint2(h01, h23);
        *reinterpret_cast<uint2*>(smem + OFF_BLO + off) = make_uint2(l01, l23);
    }
    __syncthreads();

    for (int c = 0; c < nchunks; c++) {
        const int bufoff = (c & 1) * BUF_STRIDE;
        const bool more = (c + 1 < nchunks);

        if (more) {
            const int kk = (c + 1) * KC;
#pragma unroll
            for (int i = 0; i < 4; i++) {
                int row = srow + i * 32;
                av[i] = *reinterpret_cast<const float4*>(Asrc + ((size_t)row << logw) + kk + sc4);
                bv[i] = *reinterpret_cast<const float4*>(Bsrc + ((size_t)row << logw) + kk + sc4);
            }
        }

#pragma unroll
        for (int k16 = 0; k16 < 4; k16++) {
            const uint32_t kb = bufoff + k16 * 32;
            uint32_t ah[2][4], al[2][4];
            ldsm_x4(ah[0][0], ah[0][1], ah[0][2], ah[0][3], aHi0 + kb);
            ldsm_x4(ah[1][0], ah[1][1], ah[1][2], ah[1][3], aHi0 + 16 * ROWB + kb);
            ldsm_x4(al[0][0], al[0][1], al[0][2], al[0][3], aLo0 + kb);
            ldsm_x4(al[1][0], al[1][1], al[1][2], al[1][3], aLo0 + 16 * ROWB + kb);
            uint32_t bh[4][2], bl[4][2];
#pragma unroll
            for (int q = 0; q < 2; q++) {
                uint32_t r0, r1, r2, r3;
                ldsm_x4(r0, r1, r2, r3, bHi0 + q * 16 * ROWB + kb);
                bh[2 * q][0] = r0; bh[2 * q][1] = r1;
                bh[2 * q + 1][0] = r2; bh[2 * q + 1][1] = r3;
                ldsm_x4(r0, r1, r2, r3, bLo0 + q * 16 * ROWB + kb);
                bl[2 * q][0] = r0; bl[2 * q][1] = r1;
                bl[2 * q + 1][0] = r2; bl[2 * q + 1][1] = r3;
            }
#pragma unroll
            for (int mi = 0; mi < 2; mi++)
#pragma unroll
                for (int nj = 0; nj < 4; nj++) {
                    mma_bf16(acc[mi][nj], ah[mi], bh[nj]);
                    mma_bf16(acc[mi][nj], al[mi], bh[nj]);
                    mma_bf16(acc[mi][nj], ah[mi], bl[nj]);
                }
        }

        if (more) {
            const int obuf = ((c + 1) & 1) * BUF_STRIDE;
#pragma unroll
            for (int i = 0; i < 4; i++) {
                uint32_t off = obuf + soff + i * 32 * ROWB;
                uint32_t h01, l01, h23, l23;
                split_pack(av[i].x, av[i].y, h01, l01);
                split_pack(av[i].z, av[i].w, h23, l23);
                *reinterpret_cast<uint2*>(smem + OFF_AHI + off) = make_uint2(h01, h23);
                *reinterpret_cast<uint2*>(smem + OFF_ALO + off) = make_uint2(l01, l23);
                split_pack(bv[i].x, bv[i].y, h01, l01);
                split_pack(bv[i].z, bv[i].w, h23, l23);
                *reinterpret_cast<uint2*>(smem + OFF_BHI + off) = make_uint2(h01, h23);
                *reinterpret_cast<uint2*>(smem + OFF_BLO + off) = make_uint2(l01, l23);
            }
            __syncthreads();
        }
    }

    // Epilogue
    const int col0 = (lane & 3) * 2;
    const int rbase = m0 + warp_m * 32 + (lane >> 2);
    const int ncol  = n0 + warp_n * 32;
#pragma unroll
    for (int mi = 0; mi < 2; mi++) {
        int r0 = rbase + mi * 16;
        int r1 = r0 + 8;
        bool v0 = r0 < nv, v1 = r1 < nv;
        float* o0p = outb + (size_t)r0 * kE + ncol + col0;
        float* o1p = outb + (size_t)r1 * kE + ncol + col0;
#pragma unroll
        for (int nj = 0; nj < 4; nj++) {
            float2 bias = *reinterpret_cast<const float2*>(bp + ncol + nj * 8 + col0);
            float2 o0 = v0 ? make_float2(acc[mi][nj][0] + bias.x, acc[mi][nj][1] + bias.y)
                           : make_float2(0.f, 0.f);
            float2 o1 = v1 ? make_float2(acc[mi][nj][2] + bias.x, acc[mi][nj][3] + bias.y)
                           : make_float2(0.f, 0.f);
            *reinterpret_cast<float2*>(o0p + nj * 8) = o0;
            *reinterpret_cast<float2*>(o1p + nj * 8) = o1;
        }
    }
}

// ---------------------------------------------------------------------------
extern "C" void kernel_launch(void* const* d_in, const int* in_sizes, int n_in,
                              void* d_out, int out_size)
{
    const float* signal = (const float*)d_in[0];
    const int*   mask   = (const int*)d_in[1];
    const int*   bidx   = (const int*)d_in[2];
    const float* W0 = (const float*)d_in[3];
    const float* b0 = (const float*)d_in[4];
    const float* W1 = (const float*)d_in[5];
    const float* b1 = (const float*)d_in[6];
    const float* W2 = (const float*)d_in[7];
    const float* b2 = (const float*)d_in[8];
    float* out = (float*)d_out;

    int write_mask = (out_size > kB * kSmax * kE) ? 1 : 0;

    len_mask_kernel<<<kB * 8, 256>>>(mask, bidx, out, write_mask);

    static bool attr_set = false;
    if (!attr_set) {
        cudaFuncSetAttribute(branch_gemm_mma,
                             cudaFuncAttributeMaxDynamicSharedMemorySize, SMEM_BYTES);
        attr_set = true;
    }
    dim3 grid(kE / BN, kSmax / BM, kB);
    branch_gemm_mma<<<grid, NTHREADS, SMEM_BYTES>>>(signal, bidx, W0, b0, W1, b1, W2, b2, out);
}

// round 7
// speedup vs baseline: 2.0264x; 1.0423x over previous
#include <cuda_runtime.h>
#include <cuda_bf16.h>
#include <cstdint>
#include <cstddef>

namespace {
constexpr int kB    = 128;
constexpr int kT    = 65536;
constexpr int kE    = 512;
constexpr int kSmax = 512;

constexpr int BM = 128;
constexpr int BN = 64;
constexpr int KC = 64;

constexpr int NTHREADS = 256;   // 8 warps: 4(m) x 2(n), warp tile 32x32

constexpr int LDS  = 72;
constexpr int ROWB = LDS * 2;   // 144 B/row

constexpr int OFF_AHI = 0;
constexpr int OFF_ALO = OFF_AHI + BM * ROWB;   // 18432
constexpr int OFF_BHI = OFF_ALO + BM * ROWB;   // 36864
constexpr int OFF_BLO = OFF_BHI + BN * ROWB;   // 46080
constexpr int SMEM_BYTES = OFF_BLO + BN * ROWB; // 55296
}

__device__ int g_nvalid[kB];
__device__ int g_cnt[kB];
__device__ int g_done[kB];

// ---------------------------------------------------------------------------
__device__ __forceinline__ uint32_t smem_u32(const void* p) {
    uint32_t a;
    asm("{ .reg .u64 t; cvta.to.shared.u64 t, %1; cvt.u32.u64 %0, t; }" : "=r"(a) : "l"(p));
    return a;
}

__device__ __forceinline__ void ldsm_x4(uint32_t& r0, uint32_t& r1, uint32_t& r2,
                                        uint32_t& r3, uint32_t addr) {
    asm volatile("ldmatrix.sync.aligned.m8n8.x4.shared.b16 {%0,%1,%2,%3}, [%4];"
                 : "=r"(r0), "=r"(r1), "=r"(r2), "=r"(r3) : "r"(addr));
}

__device__ __forceinline__ void mma_bf16(float* c, const uint32_t* a, const uint32_t* b) {
    asm volatile(
        "mma.sync.aligned.m16n8k16.row.col.f32.bf16.bf16.f32 "
        "{%0,%1,%2,%3}, {%4,%5,%6,%7}, {%8,%9}, {%0,%1,%2,%3};"
        : "+f"(c[0]), "+f"(c[1]), "+f"(c[2]), "+f"(c[3])
        : "r"(a[0]), "r"(a[1]), "r"(a[2]), "r"(a[3]), "r"(b[0]), "r"(b[1]));
}

__device__ __forceinline__ void split_pack(float x, float y, uint32_t& hi, uint32_t& lo) {
    __nv_bfloat16 hx = __float2bfloat16(x);
    __nv_bfloat16 hy = __float2bfloat16(y);
    __nv_bfloat16 lx = __float2bfloat16(x - __bfloat162float(hx));
    __nv_bfloat16 ly = __float2bfloat16(y - __bfloat162float(hy));
    __nv_bfloat162 h; h.x = hx; h.y = hy;
    __nv_bfloat162 l; l.x = lx; l.y = ly;
    hi = *reinterpret_cast<uint32_t*>(&h);
    lo = *reinterpret_cast<uint32_t*>(&l);
}

// ---------------------------------------------------------------------------
// Kernel A: 8 blocks/sample popcount, atomic reduce; last block finalizes.
// ---------------------------------------------------------------------------
__global__ __launch_bounds__(256) void len_mask_kernel(
    const int* __restrict__ mask,
    const int* __restrict__ branch_idx,
    float* __restrict__ out,
    int write_mask)
{
    const int b = blockIdx.x >> 3;
    const int q = blockIdx.x & 7;
    const int t = threadIdx.x;

    const uint4* p = reinterpret_cast<const uint4*>(mask + (size_t)b * kT) + q * 2048;
    int sum = 0;
#pragma unroll 4
    for (int i = t; i < 2048; i += 256) {
        uint4 v = p[i];
        sum += (int)((v.x & 1u) + (v.y & 1u) + (v.z & 1u) + (v.w & 1u));
    }
#pragma unroll
    for (int o = 16; o > 0; o >>= 1) sum += __shfl_down_sync(0xffffffffu, sum, o);

    __shared__ int warp_sums[8];
    __shared__ int is_last;
    if ((t & 31) == 0) warp_sums[t >> 5] = sum;
    __syncthreads();
    if (t == 0) {
        int tot = 0;
#pragma unroll
        for (int i = 0; i < 8; i++) tot += warp_sums[i];
        atomicAdd(&g_cnt[b], tot);
        __threadfence();
        int old = atomicAdd(&g_done[b], 1);
        is_last = (old == 7);
    }
    __syncthreads();

    if (!is_last) return;

    __shared__ int nv_sh;
    if (t == 0) {
        __threadfence();
        int tot = atomicAdd(&g_cnt[b], 0);
        int bi = branch_idx[b];
        int w  = 128 << bi;
        int Sb = kT / w;
        int nv = tot / w;
        if (nv > Sb) nv = Sb;
        g_nvalid[b] = nv;
        nv_sh = nv;
        g_cnt[b]  = 0;
        g_done[b] = 0;
    }
    __syncthreads();

    if (write_mask) {
        int nv = nv_sh;
        float* mout = out + (size_t)kB * kSmax * kE + (size_t)b * kSmax;
        for (int s = t; s < kSmax; s += 256) mout[s] = (s < nv) ? 1.0f : 0.0f;
    }
}

// ---------------------------------------------------------------------------
// Kernel B: bf16-split mma.sync GEMM. 256 threads, tile 128x64, single smem
// buffer, 2 CTAs/SM (independent barrier domains decorrelate ldsm/mma bursts).
// Grid (8, 4, 128).
// ---------------------------------------------------------------------------
__global__ __launch_bounds__(NTHREADS, 2) void branch_gemm_mma(
    const float* __restrict__ signal,
    const int*   __restrict__ branch_idx,
    const float* __restrict__ W0, const float* __restrict__ b0,
    const float* __restrict__ W1, const float* __restrict__ b1,
    const float* __restrict__ W2, const float* __restrict__ b2,
    float* __restrict__ out)
{
    extern __shared__ char smem[];
    const int tid  = threadIdx.x;
    const int b    = blockIdx.z;
    const int m0   = blockIdx.y * BM;
    const int n0   = blockIdx.x * BN;

    float* outb = out + (size_t)b * kSmax * kE;
    const int nv = g_nvalid[b];

    if (m0 >= nv) {
        float4 z = make_float4(0.f, 0.f, 0.f, 0.f);
#pragma unroll
        for (int i = 0; i < 8; i++) {
            int u   = tid + i * NTHREADS;     // 2048 float4 units = 128x64 floats
            int row = u >> 4;
            int c4  = (u & 15) << 2;
            *reinterpret_cast<float4*>(outb + (size_t)(m0 + row) * kE + n0 + c4) = z;
        }
        return;
    }

    const int bi   = branch_idx[b];
    const int logw = 7 + bi;
    const int nchunks = (1 << logw) / KC;
    const float* Wp = (bi == 0) ? W0 : (bi == 1) ? W1 : W2;
    const float* bp = (bi == 0) ? b0 : (bi == 1) ? b1 : b2;
    const float* Asrc = signal + (size_t)b * kT + ((size_t)m0 << logw);
    const float* Bsrc = Wp + ((size_t)n0 << logw);

    const uint32_t sbase = smem_u32(smem);
    const int lane   = tid & 31;
    const int warp   = tid >> 5;
    const int warp_m = warp & 3;        // m offset *32
    const int warp_n = warp >> 2;       // n offset *32

    const int a_row = warp_m * 32 + (lane & 7) + ((lane >> 3) & 1) * 8;
    const int a_col = ((lane >> 4) & 1) * 8;
    const uint32_t aHi0 = sbase + OFF_AHI + a_row * ROWB + a_col * 2;
    const uint32_t aLo0 = sbase + OFF_ALO + a_row * ROWB + a_col * 2;
    const int b_row = warp_n * 32 + (lane & 7) + ((lane >> 4) & 1) * 8;
    const int b_col = ((lane >> 3) & 1) * 8;
    const uint32_t bHi0 = sbase + OFF_BHI + b_row * ROWB + b_col * 2;
    const uint32_t bLo0 = sbase + OFF_BLO + b_row * ROWB + b_col * 2;

    float acc[2][4][4];
#pragma unroll
    for (int mi = 0; mi < 2; mi++)
#pragma unroll
        for (int nj = 0; nj < 4; nj++)
#pragma unroll
            for (int q = 0; q < 4; q++) acc[mi][nj][q] = 0.f;

    // loader slot: 16 threads/row (64 cols), A: 8 slices of 16 rows, B: 4.
    const int srow = tid >> 4;
    const int sc4  = (tid & 15) << 2;
    const uint32_t soff = srow * ROWB + sc4 * 2;

    for (int c = 0; c < nchunks; c++) {
        const int kk = c * KC;
        if (c) __syncthreads();     // previous compute done before overwrite

        // fill A (128x64)
#pragma unroll
        for (int i = 0; i < 8; i++) {
            int row = srow + i * 16;
            float4 v = *reinterpret_cast<const float4*>(Asrc + ((size_t)row << logw) + kk + sc4);
            uint32_t off = soff + i * 16 * ROWB;
            uint32_t h01, l01, h23, l23;
            split_pack(v.x, v.y, h01, l01);
            split_pack(v.z, v.w, h23, l23);
            *reinterpret_cast<uint2*>(smem + OFF_AHI + off) = make_uint2(h01, h23);
            *reinterpret_cast<uint2*>(smem + OFF_ALO + off) = make_uint2(l01, l23);
        }
        // fill B (64x64)
#pragma unroll
        for (int i = 0; i < 4; i++) {
            int row = srow + i * 16;
            float4 v = *reinterpret_cast<const float4*>(Bsrc + ((size_t)row << logw) + kk + sc4);
            uint32_t off = soff + i * 16 * ROWB;
            uint32_t h01, l01, h23, l23;
            split_pack(v.x, v.y, h01, l01);
            split_pack(v.z, v.w, h23, l23);
            *reinterpret_cast<uint2*>(smem + OFF_BHI + off) = make_uint2(h01, h23);
            *reinterpret_cast<uint2*>(smem + OFF_BLO + off) = make_uint2(l01, l23);
        }
        __syncthreads();

        // compute chunk: 4 k16 steps
#pragma unroll
        for (int k16 = 0; k16 < 4; k16++) {
            const uint32_t kb = k16 * 32;
            uint32_t ah[2][4], al[2][4];
            ldsm_x4(ah[0][0], ah[0][1], ah[0][2], ah[0][3], aHi0 + kb);
            ldsm_x4(ah[1][0], ah[1][1], ah[1][2], ah[1][3], aHi0 + 16 * ROWB + kb);
            ldsm_x4(al[0][0], al[0][1], al[0][2], al[0][3], aLo0 + kb);
            ldsm_x4(al[1][0], al[1][1], al[1][2], al[1][3], aLo0 + 16 * ROWB + kb);
            uint32_t bh[4][2], bl[4][2];
#pragma unroll
            for (int q = 0; q < 2; q++) {
                uint32_t r0, r1, r2, r3;
                ldsm_x4(r0, r1, r2, r3, bHi0 + q * 16 * ROWB + kb);
                bh[2 * q][0] = r0; bh[2 * q][1] = r1;
                bh[2 * q + 1][0] = r2; bh[2 * q + 1][1] = r3;
                ldsm_x4(r0, r1, r2, r3, bLo0 + q * 16 * ROWB + kb);
                bl[2 * q][0] = r0; bl[2 * q][1] = r1;
                bl[2 * q + 1][0] = r2; bl[2 * q + 1][1] = r3;
            }
#pragma unroll
            for (int mi = 0; mi < 2; mi++)
#pragma unroll
                for (int nj = 0; nj < 4; nj++) {
                    mma_bf16(acc[mi][nj], ah[mi], bh[nj]);
                    mma_bf16(acc[mi][nj], al[mi], bh[nj]);
                    mma_bf16(acc[mi][nj], ah[mi], bl[nj]);
                }
        }
    }

    // Epilogue
    const int col0 = (lane & 3) * 2;
    const int rbase = m0 + warp_m * 32 + (lane >> 2);
    const int ncol  = n0 + warp_n * 32;
#pragma unroll
    for (int mi = 0; mi < 2; mi++) {
        int r0 = rbase + mi * 16;
        int r1 = r0 + 8;
        bool v0 = r0 < nv, v1 = r1 < nv;
        float* o0p = outb + (size_t)r0 * kE + ncol + col0;
        float* o1p = outb + (size_t)r1 * kE + ncol + col0;
#pragma unroll
        for (int nj = 0; nj < 4; nj++) {
            float2 bias = *reinterpret_cast<const float2*>(bp + ncol + nj * 8 + col0);
            float2 o0 = v0 ? make_float2(acc[mi][nj][0] + bias.x, acc[mi][nj][1] + bias.y)
                           : make_float2(0.f, 0.f);
            float2 o1 = v1 ? make_float2(acc[mi][nj][2] + bias.x, acc[mi][nj][3] + bias.y)
                           : make_float2(0.f, 0.f);
            *reinterpret_cast<float2*>(o0p + nj * 8) = o0;
            *reinterpret_cast<float2*>(o1p + nj * 8) = o1;
        }
    }
}

// ---------------------------------------------------------------------------
extern "C" void kernel_launch(void* const* d_in, const int* in_sizes, int n_in,
                              void* d_out, int out_size)
{
    const float* signal = (const float*)d_in[0];
    const int*   mask   = (const int*)d_in[1];
    const int*   bidx   = (const int*)d_in[2];
    const float* W0 = (const float*)d_in[3];
    const float* b0 = (const float*)d_in[4];
    const float* W1 = (const float*)d_in[5];
    const float* b1 = (const float*)d_in[6];
    const float* W2 = (const float*)d_in[7];
    const float* b2 = (const float*)d_in[8];
    float* out = (float*)d_out;

    int write_mask = (out_size > kB * kSmax * kE) ? 1 : 0;

    len_mask_kernel<<<kB * 8, 256>>>(mask, bidx, out, write_mask);

    static bool attr_set = false;
    if (!attr_set) {
        cudaFuncSetAttribute(branch_gemm_mma,
                             cudaFuncAttributeMaxDynamicSharedMemorySize, SMEM_BYTES);
        attr_set = true;
    }
    dim3 grid(kE / BN, kSmax / BM, kB);
    branch_gemm_mma<<<grid, NTHREADS, SMEM_BYTES>>>(signal, bidx, W0, b0, W1, b1, W2, b2, out);
}

// round 8
// speedup vs baseline: 2.1221x; 1.0472x over previous
#include <cuda_runtime.h>
#include <cuda_bf16.h>
#include <cstdint>
#include <cstddef>

namespace {
constexpr int kB    = 128;
constexpr int kT    = 65536;
constexpr int kE    = 512;
constexpr int kSmax = 512;

constexpr int BM = 128;
constexpr int BN = 64;
constexpr int KC = 64;

constexpr int NTHREADS = 256;   // 8 warps: 4(m) x 2(n), warp tile 32x32

constexpr int LDSF = 68;        // smem row stride in floats (272B; banks 4r+c -> conflict-free)

// float-unit offsets
constexpr int OFF_A = 0;                     // 128 x 68 floats
constexpr int OFF_B = BM * LDSF;             // 8704 floats in
constexpr int SMEM_FLOATS = OFF_B + BN * LDSF;   // 13056
constexpr int SMEM_BYTES  = SMEM_FLOATS * 4;     // 52224
}

__device__ int g_nvalid[kB];
__device__ int g_cnt[kB];
__device__ int g_done[kB];

// ---------------------------------------------------------------------------
__device__ __forceinline__ uint32_t f2tf32(float x) {
    uint32_t r;
    asm("cvt.rna.tf32.f32 %0, %1;" : "=r"(r) : "f"(x));
    return r;
}

__device__ __forceinline__ void mma_tf32(float* c, const uint32_t* a, const uint32_t* b) {
    asm volatile(
        "mma.sync.aligned.m16n8k8.row.col.f32.tf32.tf32.f32 "
        "{%0,%1,%2,%3}, {%4,%5,%6,%7}, {%8,%9}, {%0,%1,%2,%3};"
        : "+f"(c[0]), "+f"(c[1]), "+f"(c[2]), "+f"(c[3])
        : "r"(a[0]), "r"(a[1]), "r"(a[2]), "r"(a[3]), "r"(b[0]), "r"(b[1]));
}

// ---------------------------------------------------------------------------
// Kernel A: 8 blocks/sample popcount, atomic reduce; last block finalizes.
// ---------------------------------------------------------------------------
__global__ __launch_bounds__(256) void len_mask_kernel(
    const int* __restrict__ mask,
    const int* __restrict__ branch_idx,
    float* __restrict__ out,
    int write_mask)
{
    const int b = blockIdx.x >> 3;
    const int q = blockIdx.x & 7;
    const int t = threadIdx.x;

    const uint4* p = reinterpret_cast<const uint4*>(mask + (size_t)b * kT) + q * 2048;
    int sum = 0;
#pragma unroll 4
    for (int i = t; i < 2048; i += 256) {
        uint4 v = p[i];
        sum += (int)((v.x & 1u) + (v.y & 1u) + (v.z & 1u) + (v.w & 1u));
    }
#pragma unroll
    for (int o = 16; o > 0; o >>= 1) sum += __shfl_down_sync(0xffffffffu, sum, o);

    __shared__ int warp_sums[8];
    __shared__ int is_last;
    if ((t & 31) == 0) warp_sums[t >> 5] = sum;
    __syncthreads();
    if (t == 0) {
        int tot = 0;
#pragma unroll
        for (int i = 0; i < 8; i++) tot += warp_sums[i];
        atomicAdd(&g_cnt[b], tot);
        __threadfence();
        int old = atomicAdd(&g_done[b], 1);
        is_last = (old == 7);
    }
    __syncthreads();

    if (!is_last) return;

    __shared__ int nv_sh;
    if (t == 0) {
        __threadfence();
        int tot = atomicAdd(&g_cnt[b], 0);
        int bi = branch_idx[b];
        int w  = 128 << bi;
        int Sb = kT / w;
        int nv = tot / w;
        if (nv > Sb) nv = Sb;
        g_nvalid[b] = nv;
        nv_sh = nv;
        g_cnt[b]  = 0;
        g_done[b] = 0;
    }
    __syncthreads();

    if (write_mask) {
        int nv = nv_sh;
        float* mout = out + (size_t)kB * kSmax * kE + (size_t)b * kSmax;
        for (int s = t; s < kSmax; s += 256) mout[s] = (s < nv) ? 1.0f : 0.0f;
    }
}

// ---------------------------------------------------------------------------
// Kernel B: tf32 mma.sync GEMM. 256 threads, tile 128x64, 3 CTAs/SM.
// Grid (8, 4, 128).
// ---------------------------------------------------------------------------
__global__ __launch_bounds__(NTHREADS, 3) void branch_gemm_mma(
    const float* __restrict__ signal,
    const int*   __restrict__ branch_idx,
    const float* __restrict__ W0, const float* __restrict__ b0,
    const float* __restrict__ W1, const float* __restrict__ b1,
    const float* __restrict__ W2, const float* __restrict__ b2,
    float* __restrict__ out)
{
    extern __shared__ float smemf[];
    const int tid  = threadIdx.x;
    const int b    = blockIdx.z;
    const int m0   = blockIdx.y * BM;
    const int n0   = blockIdx.x * BN;

    float* outb = out + (size_t)b * kSmax * kE;
    const int nv = g_nvalid[b];

    if (m0 >= nv) {
        float4 z = make_float4(0.f, 0.f, 0.f, 0.f);
#pragma unroll
        for (int i = 0; i < 8; i++) {
            int u   = tid + i * NTHREADS;     // 2048 float4 = 128x64 floats
            int row = u >> 4;
            int c4  = (u & 15) << 2;
            *reinterpret_cast<float4*>(outb + (size_t)(m0 + row) * kE + n0 + c4) = z;
        }
        return;
    }

    const int bi   = branch_idx[b];
    const int logw = 7 + bi;
    const int nchunks = (1 << logw) / KC;     // 2, 4, 8
    const float* Wp = (bi == 0) ? W0 : (bi == 1) ? W1 : W2;
    const float* bp = (bi == 0) ? b0 : (bi == 1) ? b1 : b2;
    const float* Asrc = signal + (size_t)b * kT + ((size_t)m0 << logw);
    const float* Bsrc = Wp + ((size_t)n0 << logw);

    const int lane   = tid & 31;
    const int warp   = tid >> 5;
    const int warp_m = warp & 3;        // m offset *32
    const int warp_n = warp >> 2;       // n offset *32
    const int g      = lane >> 2;       // groupID 0..7
    const int tg     = lane & 3;        // thread-in-group

    // fragment base indices (float units)
    const uint32_t aBase = OFF_A + (warp_m * 32 + g) * LDSF + tg;
    const uint32_t bBase = OFF_B + (warp_n * 32 + g) * LDSF + tg;

    float acc[2][4][4];
#pragma unroll
    for (int mi = 0; mi < 2; mi++)
#pragma unroll
        for (int nj = 0; nj < 4; nj++)
#pragma unroll
            for (int q = 0; q < 4; q++) acc[mi][nj][q] = 0.f;

    // loader: 16 threads/row, float4 per thread
    const int srow = tid >> 4;
    const int sc4  = (tid & 15) << 2;

    for (int c = 0; c < nchunks; c++) {
        const int kk = c * KC;
        if (c) __syncthreads();

        // fill A (128 x 64)
#pragma unroll
        for (int i = 0; i < 8; i++) {
            int row = srow + i * 16;
            float4 v = *reinterpret_cast<const float4*>(Asrc + ((size_t)row << logw) + kk + sc4);
            uint32_t* d = reinterpret_cast<uint32_t*>(smemf + OFF_A + row * LDSF + sc4);
            uint4 t4 = make_uint4(f2tf32(v.x), f2tf32(v.y), f2tf32(v.z), f2tf32(v.w));
            *reinterpret_cast<uint4*>(d) = t4;
        }
        // fill B (64 x 64)
#pragma unroll
        for (int i = 0; i < 4; i++) {
            int row = srow + i * 16;
            float4 v = *reinterpret_cast<const float4*>(Bsrc + ((size_t)row << logw) + kk + sc4);
            uint32_t* d = reinterpret_cast<uint32_t*>(smemf + OFF_B + row * LDSF + sc4);
            uint4 t4 = make_uint4(f2tf32(v.x), f2tf32(v.y), f2tf32(v.z), f2tf32(v.w));
            *reinterpret_cast<uint4*>(d) = t4;
        }
        __syncthreads();

        // compute: 8 k8 steps
        const uint32_t* sm = reinterpret_cast<const uint32_t*>(smemf);
#pragma unroll
        for (int s = 0; s < 8; s++) {
            const uint32_t ko = s * 8;
            uint32_t af[2][4], bf[4][2];
#pragma unroll
            for (int mi = 0; mi < 2; mi++) {
                uint32_t base = aBase + mi * 16 * LDSF + ko;
                af[mi][0] = sm[base];
                af[mi][1] = sm[base + 8 * LDSF];
                af[mi][2] = sm[base + 4];
                af[mi][3] = sm[base + 8 * LDSF + 4];
            }
#pragma unroll
            for (int nj = 0; nj < 4; nj++) {
                uint32_t base = bBase + nj * 8 * LDSF + ko;
                bf[nj][0] = sm[base];
                bf[nj][1] = sm[base + 4];
            }
#pragma unroll
            for (int mi = 0; mi < 2; mi++)
#pragma unroll
                for (int nj = 0; nj < 4; nj++)
                    mma_tf32(acc[mi][nj], af[mi], bf[nj]);
        }
    }

    // Epilogue
    const int col0 = tg * 2;
    const int rbase = m0 + warp_m * 32 + g;
    const int ncol  = n0 + warp_n * 32;
#pragma unroll
    for (int mi = 0; mi < 2; mi++) {
        int r0 = rbase + mi * 16;
        int r1 = r0 + 8;
        bool v0 = r0 < nv, v1 = r1 < nv;
        float* o0p = outb + (size_t)r0 * kE + ncol + col0;
        float* o1p = outb + (size_t)r1 * kE + ncol + col0;
#pragma unroll
        for (int nj = 0; nj < 4; nj++) {
            float2 bias = *reinterpret_cast<const float2*>(bp + ncol + nj * 8 + col0);
            float2 o0 = v0 ? make_float2(acc[mi][nj][0] + bias.x, acc[mi][nj][1] + bias.y)
                           : make_float2(0.f, 0.f);
            float2 o1 = v1 ? make_float2(acc[mi][nj][2] + bias.x, acc[mi][nj][3] + bias.y)
                           : make_float2(0.f, 0.f);
            *reinterpret_cast<float2*>(o0p + nj * 8) = o0;
            *reinterpret_cast<float2*>(o1p + nj * 8) = o1;
        }
    }
}

// ---------------------------------------------------------------------------
extern "C" void kernel_launch(void* const* d_in, const int* in_sizes, int n_in,
                              void* d_out, int out_size)
{
    const float* signal = (const float*)d_in[0];
    const int*   mask   = (const int*)d_in[1];
    const int*   bidx   = (const int*)d_in[2];
    const float* W0 = (const float*)d_in[3];
    const float* b0 = (const float*)d_in[4];
    const float* W1 = (const float*)d_in[5];
    const float* b1 = (const float*)d_in[6];
    const float* W2 = (const float*)d_in[7];
    const float* b2 = (const float*)d_in[8];
    float* out = (float*)d_out;

    int write_mask = (out_size > kB * kSmax * kE) ? 1 : 0;

    len_mask_kernel<<<kB * 8, 256>>>(mask, bidx, out, write_mask);

    static bool attr_set = false;
    if (!attr_set) {
        cudaFuncSetAttribute(branch_gemm_mma,
                             cudaFuncAttributeMaxDynamicSharedMemorySize, SMEM_BYTES);
        attr_set = true;
    }
    dim3 grid(kE / BN, kSmax / BM, kB);
    branch_gemm_mma<<<grid, NTHREADS, SMEM_BYTES>>>(signal, bidx, W0, b0, W1, b1, W2, b2, out);
}